// round 4
// baseline (speedup 1.0000x reference)
#include <cuda_runtime.h>
#include <cstdint>

// softmax_rgb_blend (pytorch3d) — N=8, H=512, W=512, K=8
// inputs (metadata order):
//   d_in[0] pixel_colors f32 [N,H,W,K,3]  (96 B / pixel, 16B-aligned stride)
//   d_in[1] zbuf         f32 [N,H,W,K]    (32 B / pixel)
//   d_in[2] dists        f32 [N,H,W,K]    (32 B / pixel)
//   d_in[3] pix_to_face  i32 [N,H,W,K]    (32 B / pixel)
// output: f32 [N,H,W,4]
//
// Pure HBM-bound: ~436 MB total traffic, zero reuse. One thread per pixel,
// everything loaded as float4/int4 (fully coalesced: warp covers contiguous
// 1KB/3KB regions), 12 independent loads in flight per thread.

#define SIGMA_F   1e-4f
#define GAMMA_F   1e-4f
#define ZNEAR_F   1.0f
#define ZFAR_F    100.0f
#define EPS_F     1e-10f

__global__ __launch_bounds__(256)
void blend_kernel(const float4* __restrict__ colors4,  // npix * 6
                  const float4* __restrict__ zbuf4,    // npix * 2
                  const float4* __restrict__ dists4,   // npix * 2
                  const int4*   __restrict__ ptf4,     // npix * 2
                  float4*       __restrict__ out4,     // npix
                  int npix)
{
    int p = blockIdx.x * blockDim.x + threadIdx.x;
    if (p >= npix) return;

    // ---- issue all loads up front (MLP ~ 12) ----
    float4 z0 = zbuf4[2 * p + 0];
    float4 z1 = zbuf4[2 * p + 1];
    float4 d0 = dists4[2 * p + 0];
    float4 d1 = dists4[2 * p + 1];
    int4   f0 = ptf4[2 * p + 0];
    int4   f1 = ptf4[2 * p + 1];

    float4 c4[6];
#pragma unroll
    for (int i = 0; i < 6; i++) c4[i] = colors4[6 * p + i];

    float zb[8] = {z0.x, z0.y, z0.z, z0.w, z1.x, z1.y, z1.z, z1.w};
    float ds[8] = {d0.x, d0.y, d0.z, d0.w, d1.x, d1.y, d1.z, d1.w};
    int   pf[8] = {f0.x, f0.y, f0.z, f0.w, f1.x, f1.y, f1.z, f1.w};

    // ---- pass 1: prob, z_inv, running max + silhouette product ----
    float prob[8], zinv[8];
    float zmax = EPS_F;
    float one_minus_prod = 1.0f;
#pragma unroll
    for (int k = 0; k < 8; k++) {
        float m = (pf[k] >= 0) ? 1.0f : 0.0f;
        // sigmoid(-dists/sigma) = 1 / (1 + exp(dists/sigma))
        float pr = (1.0f / (1.0f + expf(ds[k] / SIGMA_F))) * m;
        prob[k] = pr;
        one_minus_prod *= (1.0f - pr);
        float zi = (ZFAR_F - zb[k]) / (ZFAR_F - ZNEAR_F) * m;
        zinv[k] = zi;
        zmax = fmaxf(zmax, zi);
    }
    float alpha = 1.0f - one_minus_prod;

    // ---- pass 2: softmax weights ----
    float w[8];
    float wsum = 0.0f;
#pragma unroll
    for (int k = 0; k < 8; k++) {
        float wk = prob[k] * expf((zinv[k] - zmax) / GAMMA_F);
        w[k] = wk;
        wsum += wk;
    }
    float delta = expf((EPS_F - zmax) / GAMMA_F);
    float inv_denom = 1.0f / (wsum + delta);

    // ---- pass 3: weighted color accumulation ----
    const float* cc = reinterpret_cast<const float*>(c4);  // 24 floats: [k][c]
    float r = 0.0f, g = 0.0f, b = 0.0f;
#pragma unroll
    for (int k = 0; k < 8; k++) {
        r = fmaf(w[k], cc[3 * k + 0], r);
        g = fmaf(w[k], cc[3 * k + 1], g);
        b = fmaf(w[k], cc[3 * k + 2], b);
    }
    // background color = (1,1,1): rgb = (acc + delta*1) / denom
    float4 o;
    o.x = (r + delta) * inv_denom;
    o.y = (g + delta) * inv_denom;
    o.z = (b + delta) * inv_denom;
    o.w = alpha;
    out4[p] = o;
}

extern "C" void kernel_launch(void* const* d_in, const int* in_sizes, int n_in,
                              void* d_out, int out_size)
{
    const float4* colors4 = (const float4*)d_in[0];
    const float4* zbuf4   = (const float4*)d_in[1];
    const float4* dists4  = (const float4*)d_in[2];
    const int4*   ptf4    = (const int4*)d_in[3];
    float4*       out4    = (float4*)d_out;

    int npix = out_size / 4;  // [N,H,W,4] -> one float4 per pixel
    int threads = 256;
    int blocks = (npix + threads - 1) / threads;
    blend_kernel<<<blocks, threads>>>(colors4, zbuf4, dists4, ptf4, out4, npix);
}

// round 5
// speedup vs baseline: 1.1207x; 1.1207x over previous
#include <cuda_runtime.h>
#include <cstdint>

// softmax_rgb_blend (pytorch3d) — N=8, H=512, W=512, K=8
// inputs (metadata order):
//   d_in[0] pixel_colors f32 [N,H,W,K,3]  (96 B / pixel)
//   d_in[1] zbuf         f32 [N,H,W,K]    (32 B / pixel)
//   d_in[2] dists        f32 [N,H,W,K]    (32 B / pixel)
//   d_in[3] pix_to_face  i32 [N,H,W,K]    (32 B / pixel)
// output: f32 [N,H,W,4]  (16 B / pixel)
//
// HBM-bound (~436 MB, zero reuse). R4 showed issue=76% / DRAM=68%:
// IEEE expf was eating issue slots. This round: __expf / __fdividef
// fast paths, constants folded to multiplies.

#define INV_SIGMA   1.0e4f            // 1/1e-4
#define INV_GAMMA   1.0e4f            // 1/1e-4
#define INV_ZRANGE  (1.0f / 99.0f)    // 1/(zfar - znear)
#define ZFAR_F      100.0f
#define EPS_F       1e-10f

__global__ __launch_bounds__(256)
void blend_kernel(const float4* __restrict__ colors4,  // npix * 6
                  const float4* __restrict__ zbuf4,    // npix * 2
                  const float4* __restrict__ dists4,   // npix * 2
                  const int4*   __restrict__ ptf4,     // npix * 2
                  float4*       __restrict__ out4,     // npix
                  int npix)
{
    int p = blockIdx.x * blockDim.x + threadIdx.x;
    if (p >= npix) return;

    // ---- issue all loads up front (MLP ~ 12) ----
    float4 z0 = zbuf4[2 * p + 0];
    float4 z1 = zbuf4[2 * p + 1];
    float4 d0 = dists4[2 * p + 0];
    float4 d1 = dists4[2 * p + 1];
    int4   f0 = ptf4[2 * p + 0];
    int4   f1 = ptf4[2 * p + 1];

    float4 c4[6];
#pragma unroll
    for (int i = 0; i < 6; i++) c4[i] = colors4[6 * p + i];

    float zb[8] = {z0.x, z0.y, z0.z, z0.w, z1.x, z1.y, z1.z, z1.w};
    float ds[8] = {d0.x, d0.y, d0.z, d0.w, d1.x, d1.y, d1.z, d1.w};
    int   pf[8] = {f0.x, f0.y, f0.z, f0.w, f1.x, f1.y, f1.z, f1.w};

    // ---- pass 1: prob, z_inv, running max + silhouette product ----
    float prob[8], zinv[8];
    float zmax = EPS_F;
    float one_minus_prod = 1.0f;
#pragma unroll
    for (int k = 0; k < 8; k++) {
        float m = (pf[k] >= 0) ? 1.0f : 0.0f;
        // sigmoid(-d/sigma) = 1 / (1 + exp(d/sigma))   (fast path: MUFU.EX2 + MUFU.RCP)
        float e = __expf(ds[k] * INV_SIGMA);
        float pr = __fdividef(1.0f, 1.0f + e) * m;
        prob[k] = pr;
        one_minus_prod *= (1.0f - pr);
        float zi = (ZFAR_F - zb[k]) * INV_ZRANGE * m;
        zinv[k] = zi;
        zmax = fmaxf(zmax, zi);
    }
    float alpha = 1.0f - one_minus_prod;

    // ---- pass 2: softmax weights ----
    float w[8];
    float wsum = 0.0f;
#pragma unroll
    for (int k = 0; k < 8; k++) {
        float wk = prob[k] * __expf((zinv[k] - zmax) * INV_GAMMA);
        w[k] = wk;
        wsum += wk;
    }
    float delta = __expf((EPS_F - zmax) * INV_GAMMA);
    float inv_denom = __fdividef(1.0f, wsum + delta);

    // ---- pass 3: weighted color accumulation ----
    const float* cc = reinterpret_cast<const float*>(c4);  // 24 floats: [k][c]
    float r = 0.0f, g = 0.0f, b = 0.0f;
#pragma unroll
    for (int k = 0; k < 8; k++) {
        r = fmaf(w[k], cc[3 * k + 0], r);
        g = fmaf(w[k], cc[3 * k + 1], g);
        b = fmaf(w[k], cc[3 * k + 2], b);
    }
    // background color = (1,1,1): rgb = (acc + delta*1) * inv_denom
    float4 o;
    o.x = (r + delta) * inv_denom;
    o.y = (g + delta) * inv_denom;
    o.z = (b + delta) * inv_denom;
    o.w = alpha;
    out4[p] = o;
}

extern "C" void kernel_launch(void* const* d_in, const int* in_sizes, int n_in,
                              void* d_out, int out_size)
{
    const float4* colors4 = (const float4*)d_in[0];
    const float4* zbuf4   = (const float4*)d_in[1];
    const float4* dists4  = (const float4*)d_in[2];
    const int4*   ptf4    = (const int4*)d_in[3];
    float4*       out4    = (float4*)d_out;

    int npix = out_size / 4;  // [N,H,W,4] -> one float4 per pixel
    int threads = 256;
    int blocks = (npix + threads - 1) / threads;
    blend_kernel<<<blocks, threads>>>(colors4, zbuf4, dists4, ptf4, out4, npix);
}

// round 6
// speedup vs baseline: 1.2238x; 1.0921x over previous
#include <cuda_runtime.h>
#include <cstdint>

// softmax_rgb_blend (pytorch3d) — N=8, H=512, W=512, K=8
// inputs: colors f32[N,H,W,K,3], zbuf f32[N,H,W,K], dists f32[N,H,W,K], ptf i32[N,H,W,K]
// output: f32 [N,H,W,4]
//
// HBM-bound (~436 MB, zero reuse). R5: regs=32 forced local spills (~45 live
// values). This round: fused weight+color pass (no w[8] array), reg cap 51 via
// launch_bounds(256,5), streaming ld/st hints, raw EX2 with folded log2e.

#define SIGMA_L2E   14426.950408889634f   // (1/1e-4) * log2(e)
#define GAMMA_L2E   14426.950408889634f   // (1/1e-4) * log2(e)
#define INV_ZRANGE  (1.0f / 99.0f)        // 1/(zfar - znear)
#define ZFAR_F      100.0f
#define EPS_F       1e-10f

__device__ __forceinline__ float ex2(float x) {
    float y;
    asm("ex2.approx.ftz.f32 %0, %1;" : "=f"(y) : "f"(x));
    return y;
}

__global__ __launch_bounds__(256, 5)
void blend_kernel(const float4* __restrict__ colors4,  // npix * 6
                  const float4* __restrict__ zbuf4,    // npix * 2
                  const float4* __restrict__ dists4,   // npix * 2
                  const int4*   __restrict__ ptf4,     // npix * 2
                  float4*       __restrict__ out4,     // npix
                  int npix)
{
    int p = blockIdx.x * blockDim.x + threadIdx.x;
    if (p >= npix) return;

    // ---- issue all loads up front (MLP ~ 12), evict-first (zero reuse) ----
    float4 z0 = __ldcs(zbuf4 + 2 * p + 0);
    float4 z1 = __ldcs(zbuf4 + 2 * p + 1);
    float4 d0 = __ldcs(dists4 + 2 * p + 0);
    float4 d1 = __ldcs(dists4 + 2 * p + 1);
    int4   f0 = __ldcs(ptf4 + 2 * p + 0);
    int4   f1 = __ldcs(ptf4 + 2 * p + 1);

    float4 c4[6];
#pragma unroll
    for (int i = 0; i < 6; i++) c4[i] = __ldcs(colors4 + 6 * p + i);

    float zb[8] = {z0.x, z0.y, z0.z, z0.w, z1.x, z1.y, z1.z, z1.w};
    float ds[8] = {d0.x, d0.y, d0.z, d0.w, d1.x, d1.y, d1.z, d1.w};
    int   pf[8] = {f0.x, f0.y, f0.z, f0.w, f1.x, f1.y, f1.z, f1.w};

    // ---- pass 1: prob, z_inv, running max + silhouette product ----
    float prob[8], zinv[8];
    float zmax = EPS_F;
    float one_minus_prod = 1.0f;
#pragma unroll
    for (int k = 0; k < 8; k++) {
        float m = (pf[k] >= 0) ? 1.0f : 0.0f;
        // sigmoid(-d/sigma)*m = m / (1 + exp2(d * sigma_log2e))
        float e = ex2(ds[k] * SIGMA_L2E);
        float pr = __fdividef(m, 1.0f + e);
        prob[k] = pr;
        one_minus_prod *= (1.0f - pr);
        float zi = fmaf(-zb[k], INV_ZRANGE, ZFAR_F * INV_ZRANGE) * m;
        zinv[k] = zi;
        zmax = fmaxf(zmax, zi);
    }
    float alpha = 1.0f - one_minus_prod;

    // ---- fused pass 2+3: unnormalized weights -> color accumulation ----
    const float* cc = reinterpret_cast<const float*>(c4);  // 24 floats: [k][c]
    float wsum = 0.0f, r = 0.0f, g = 0.0f, b = 0.0f;
#pragma unroll
    for (int k = 0; k < 8; k++) {
        float wk = prob[k] * ex2((zinv[k] - zmax) * GAMMA_L2E);
        wsum += wk;
        r = fmaf(wk, cc[3 * k + 0], r);
        g = fmaf(wk, cc[3 * k + 1], g);
        b = fmaf(wk, cc[3 * k + 2], b);
    }
    float delta = ex2((EPS_F - zmax) * GAMMA_L2E);
    float inv_denom = __fdividef(1.0f, wsum + delta);

    // background color = (1,1,1): rgb = (acc + delta*1) * inv_denom
    float4 o;
    o.x = (r + delta) * inv_denom;
    o.y = (g + delta) * inv_denom;
    o.z = (b + delta) * inv_denom;
    o.w = alpha;
    __stcs(out4 + p, o);
}

extern "C" void kernel_launch(void* const* d_in, const int* in_sizes, int n_in,
                              void* d_out, int out_size)
{
    const float4* colors4 = (const float4*)d_in[0];
    const float4* zbuf4   = (const float4*)d_in[1];
    const float4* dists4  = (const float4*)d_in[2];
    const int4*   ptf4    = (const int4*)d_in[3];
    float4*       out4    = (float4*)d_out;

    int npix = out_size / 4;  // [N,H,W,4] -> one float4 per pixel
    int threads = 256;
    int blocks = (npix + threads - 1) / threads;
    blend_kernel<<<blocks, threads>>>(colors4, zbuf4, dists4, ptf4, out4, npix);
}